// round 17
// baseline (speedup 1.0000x reference)
#include <cuda_runtime.h>
#include <cuda_fp16.h>
#include <cstdint>
#include <math.h>

constexpr int SEQ = 2048, DIM = 2048, NH = 16, NKV = 4, HD = 128, FF = 8192;
constexpr int QKVN = NH * HD + 2 * NKV * HD;   // 3072
constexpr float EPSV = 1e-6f;

// ---------------------------------------------------------------------------
// Scratch (device globals — allocation forbidden)
// ---------------------------------------------------------------------------
__device__ __half g_h1h [SEQ * DIM];
__device__ __half g_qkvh[SEQ * QKVN];            // q | k | v packed per row
__device__ __half g_ath [SEQ * NH * HD];
__device__ float  g_x2  [SEQ * DIM];
__device__ __half g_h2h [SEQ * DIM];
__device__ __half g_mmh [(long)SEQ * FF];
__device__ __half g_Wqkv16[(long)DIM * QKVN];    // [K=2048][N=3072] row-major
__device__ __half g_Wo16[DIM * DIM];             // [K][N] native layout
__device__ __half g_Wg16[(long)DIM * FF];
__device__ __half g_Wu16[(long)DIM * FF];
__device__ __half g_Wd16[(long)FF * DIM];
__device__ double g_invf[64];
__device__ float2 g_cs[SEQ * 64];

// ---------------------------------------------------------------------------
__device__ __forceinline__ uint32_t smem_u32(const void* p) {
    uint32_t a;
    asm("{ .reg .u64 t; cvta.to.shared.u64 t, %1; cvt.u32.u64 %0, t; }" : "=r"(a) : "l"(p));
    return a;
}
__device__ __forceinline__ void cp16(uint32_t dst, const void* src) {
    asm volatile("cp.async.cg.shared.global [%0], [%1], 16;" :: "r"(dst), "l"(src) : "memory");
}
__device__ __forceinline__ void cp_commit() {
    asm volatile("cp.async.commit_group;" ::: "memory");
}
template<int N> __device__ __forceinline__ void cp_wait() {
    asm volatile("cp.async.wait_group %0;" :: "n"(N) : "memory");
}
__device__ __forceinline__ void mma_f16(float* c, const uint32_t* a, const uint32_t* b) {
    asm volatile(
        "mma.sync.aligned.m16n8k16.row.col.f32.f16.f16.f32 "
        "{%0,%1,%2,%3}, {%4,%5,%6,%7}, {%8,%9}, {%0,%1,%2,%3};"
        : "+f"(c[0]), "+f"(c[1]), "+f"(c[2]), "+f"(c[3])
        : "r"(a[0]), "r"(a[1]), "r"(a[2]), "r"(a[3]), "r"(b[0]), "r"(b[1]));
}
__device__ __forceinline__ void ldsm_x4(uint32_t* r, uint32_t addr) {
    asm volatile("ldmatrix.sync.aligned.m8n8.x4.shared.b16 {%0,%1,%2,%3}, [%4];"
                 : "=r"(r[0]), "=r"(r[1]), "=r"(r[2]), "=r"(r[3]) : "r"(addr));
}
__device__ __forceinline__ void ldsm_x4_t(uint32_t* r, uint32_t addr) {
    asm volatile("ldmatrix.sync.aligned.m8n8.x4.trans.shared.b16 {%0,%1,%2,%3}, [%4];"
                 : "=r"(r[0]), "=r"(r[1]), "=r"(r[2]), "=r"(r[3]) : "r"(addr));
}

__device__ __forceinline__ float fexp(float x) {  // accurate for x <= 0
    float t = x * 1.4426950408889634f;
    float r = rintf(t), f = t - r;
    int i = (int)r;
    float p = 0.0013333558f;
    p = fmaf(p, f, 0.0096181291f);
    p = fmaf(p, f, 0.0555041087f);
    p = fmaf(p, f, 0.2402264476f);
    p = fmaf(p, f, 0.6931471806f);
    p = fmaf(p, f, 1.0f);
    float s = __int_as_float((i + 127) << 23);
    return (x < -80.f) ? 0.f : p * s;
}
__device__ __forceinline__ float silu(float g) {
    float t = fexp(-fabsf(g));
    float s = (g >= 0.f) ? 1.f / (1.f + t) : t / (1.f + t);
    return g * s;
}

// ---------------- streaming fp32 -> fp16 convert (no transpose) ------------
__global__ __launch_bounds__(256)
void convert_wh(const float* __restrict__ in, __half* __restrict__ out,
                int R, int C, int ldout) {
    const long total = (long)R * (C >> 2);
    const int cq = C >> 2;
    for (long idx = (long)blockIdx.x * 256 + threadIdx.x; idx < total;
         idx += (long)gridDim.x * 256) {
        long r = idx / cq;
        int c4 = (int)(idx - r * cq) * 4;
        float4 v = *(const float4*)&in[r * C + c4];
        __half* o = out + r * ldout + c4;
        *(__half2*)o       = __floats2half2_rn(v.x, v.y);
        *(__half2*)(o + 2) = __floats2half2_rn(v.z, v.w);
    }
}

// ---------------- rmsnorm (fp16 out) ---------------------------------------
__global__ __launch_bounds__(256)
void rmsnorm_h(const float* __restrict__ x, const float* __restrict__ w,
               __half* __restrict__ o) {
    const int row = blockIdx.x;
    const float* xr = x + (size_t)row * DIM;
    float s = 0.f;
    for (int j = threadIdx.x; j < DIM; j += 256) { float v = xr[j]; s += v * v; }
    __shared__ float red[256];
    red[threadIdx.x] = s;
    __syncthreads();
    for (int st = 128; st > 0; st >>= 1) {
        if (threadIdx.x < st) red[threadIdx.x] += red[threadIdx.x + st];
        __syncthreads();
    }
    const float inv = rsqrtf(red[0] * (1.0f / DIM) + EPSV);
    __half* orow = o + (size_t)row * DIM;
    for (int j = threadIdx.x; j < DIM; j += 256)
        orow[j] = __float2half_rn(xr[j] * inv * w[j]);
}

// ---------------- RoPE -----------------------------------------------------
__global__ void init_invf_kernel() { g_invf[threadIdx.x] = pow(10000.0, -(double)threadIdx.x / 64.0); }
__global__ void rope_table_kernel() {
    int s = blockIdx.x, d = threadIdx.x;
    double ang = (double)s * g_invf[d];
    const double twopi = 6.283185307179586476925287;
    double r = ang - twopi * floor(ang / twopi + 0.5);
    float rf = (float)r;
    g_cs[s * 64 + d] = make_float2(cosf(rf), sinf(rf));
}
__global__ void rope_apply_h(__half* __restrict__ qkv) {
    const int s = blockIdx.x, h = blockIdx.y, d = threadIdx.x;
    __half* base = qkv + (size_t)s * QKVN +
                   ((h < NH) ? h * HD : (NH * HD + (h - NH) * HD));
    float2 cs = g_cs[s * 64 + d];
    float x0 = __half2float(base[d]), x1 = __half2float(base[d + 64]);
    base[d]      = __float2half_rn(x0 * cs.x - x1 * cs.y);
    base[d + 64] = __float2half_rn(x1 * cs.x + x0 * cs.y);
}

// ---------------------------------------------------------------------------
// Flash attention (R14-passing): one CTA = (128 q-rows, 1 head).
// ---------------------------------------------------------------------------
constexpr int FL_SMEM = 32768 + 2 * 32768;   // 98304

__global__ __launch_bounds__(256, 2)
void flash_attn(const __half* __restrict__ qkv, __half* __restrict__ outh,
                float iscale) {
    const int qt = (int)(gridDim.x - 1 - blockIdx.x);
    const int h  = blockIdx.y;
    const int row0 = qt * 128;
    const __half* Qg = qkv + h * HD;
    const __half* Kg = qkv + NH * HD + (h >> 2) * HD;
    const __half* Vg = qkv + NH * HD + NKV * HD + (h >> 2) * HD;

    extern __shared__ char smc[];
    const uint32_t smQ = smem_u32(smc);

    const int tid = threadIdx.x, wid = tid >> 5, lane = tid & 31;
    const int lr = lane >> 2, lc = lane & 3, l7 = lane & 7;
    const int wrow = wid * 16;

    for (int j = 0; j < 8; j++) {
        int idx = j * 256 + tid, r = idx >> 4, c = idx & 15;
        uint32_t sw = (uint32_t)((c ^ (r & 7)) * 16);
        cp16(smQ + (uint32_t)r * 256 + sw, Qg + (size_t)(row0 + r) * QKVN + c * 8);
    }
    cp_commit();

    auto stageKV = [&](int s, int kt) {
        const uint32_t kB = smQ + 32768u + (uint32_t)s * 32768u;
        const uint32_t vB = kB + 16384u;
        for (int j = 0; j < 4; j++) {
            int idx = j * 256 + tid, r = idx >> 4, c = idx & 15;
            uint32_t sw = (uint32_t)((c ^ (r & 7)) * 16);
            cp16(kB + (uint32_t)r * 256 + sw, Kg + (size_t)(kt * 64 + r) * QKVN + c * 8);
            cp16(vB + (uint32_t)r * 256 + sw, Vg + (size_t)(kt * 64 + r) * QKVN + c * 8);
        }
    };

    const int nkt = 2 * qt + 2;
    stageKV(0, 0);
    cp_commit();
    if (nkt > 1) { stageKV(1, 1); cp_commit(); }

    float Oacc[16][4];
#pragma unroll
    for (int nt = 0; nt < 16; nt++)
#pragma unroll
        for (int i = 0; i < 4; i++) Oacc[nt][i] = 0.f;
    float m0 = -1e30f, m1 = -1e30f, l0 = 0.f, l1 = 0.f;

    const int aRow = wrow + ((lane >> 3) & 1) * 8 + l7;
    const int aSel = (lane >> 4) & 1;
    const int bRowB = ((lane >> 4) & 1) * 8 + l7;
    const int bSel = (lane >> 3) & 1;
    const int grow0 = row0 + wrow + lr;
    const int vg = lane >> 3;
    const int vsub = vg & 1, vnq = vg >> 1;

    for (int kt = 0; kt < nkt; kt++) {
        if (kt == nkt - 1) cp_wait<0>(); else cp_wait<1>();
        __syncthreads();
        const uint32_t kB = smQ + 32768u + (uint32_t)(kt & 1) * 32768u;
        const uint32_t vB = kB + 16384u;

        float S[8][4];
#pragma unroll
        for (int nt = 0; nt < 8; nt++)
#pragma unroll
            for (int i = 0; i < 4; i++) S[nt][i] = 0.f;

#pragma unroll
        for (int dc = 0; dc < 8; dc++) {
            uint32_t qf[4];
            ldsm_x4(qf, smQ + (uint32_t)aRow * 256 +
                        (uint32_t)(((dc * 2 + aSel) ^ l7) * 16));
#pragma unroll
            for (int np = 0; np < 4; np++) {
                uint32_t kf[4];
                ldsm_x4(kf, kB + (uint32_t)(np * 16 + bRowB) * 256 +
                            (uint32_t)(((dc * 2 + bSel) ^ l7) * 16));
                mma_f16(S[np * 2],     qf, kf);
                mma_f16(S[np * 2 + 1], qf, kf + 2);
            }
        }

        const bool diag = (kt >= 2 * qt);
#pragma unroll
        for (int nt = 0; nt < 8; nt++) {
            int c0 = kt * 64 + nt * 8 + lc * 2;
            S[nt][0] *= iscale; S[nt][1] *= iscale;
            S[nt][2] *= iscale; S[nt][3] *= iscale;
            if (diag) {
                if (c0     > grow0)     S[nt][0] = -1e30f;
                if (c0 + 1 > grow0)     S[nt][1] = -1e30f;
                if (c0     > grow0 + 8) S[nt][2] = -1e30f;
                if (c0 + 1 > grow0 + 8) S[nt][3] = -1e30f;
            }
        }

        float r0 = -1e30f, r1 = -1e30f;
#pragma unroll
        for (int nt = 0; nt < 8; nt++) {
            r0 = fmaxf(r0, fmaxf(S[nt][0], S[nt][1]));
            r1 = fmaxf(r1, fmaxf(S[nt][2], S[nt][3]));
        }
        r0 = fmaxf(r0, __shfl_xor_sync(0xffffffff, r0, 1));
        r0 = fmaxf(r0, __shfl_xor_sync(0xffffffff, r0, 2));
        r1 = fmaxf(r1, __shfl_xor_sync(0xffffffff, r1, 1));
        r1 = fmaxf(r1, __shfl_xor_sync(0xffffffff, r1, 2));
        const float mn0 = fmaxf(m0, r0), mn1 = fmaxf(m1, r1);
        const float sc0 = fexp(m0 - mn0), sc1 = fexp(m1 - mn1);
        m0 = mn0; m1 = mn1;

        uint32_t (*Su)[4] = (uint32_t(*)[4])S;
        float sum0 = 0.f, sum1 = 0.f;
#pragma unroll
        for (int nt = 0; nt < 8; nt++) {
            float e0 = fexp(S[nt][0] - mn0), e1 = fexp(S[nt][1] - mn0);
            float e2 = fexp(S[nt][2] - mn1), e3 = fexp(S[nt][3] - mn1);
            sum0 += e0 + e1; sum1 += e2 + e3;
            __half2 p01 = __floats2half2_rn(e0, e1);
            __half2 p23 = __floats2half2_rn(e2, e3);
            Su[nt][0] = *(uint32_t*)&p01;
            Su[nt][1] = *(uint32_t*)&p23;
        }
        sum0 += __shfl_xor_sync(0xffffffff, sum0, 1);
        sum0 += __shfl_xor_sync(0xffffffff, sum0, 2);
        sum1 += __shfl_xor_sync(0xffffffff, sum1, 1);
        sum1 += __shfl_xor_sync(0xffffffff, sum1, 2);
        l0 = l0 * sc0 + sum0;
        l1 = l1 * sc1 + sum1;

#pragma unroll
        for (int nt = 0; nt < 16; nt++) {
            Oacc[nt][0] *= sc0; Oacc[nt][1] *= sc0;
            Oacc[nt][2] *= sc1; Oacc[nt][3] *= sc1;
        }

#pragma unroll
        for (int kc = 0; kc < 4; kc++) {
            uint32_t aP[4] = { Su[2 * kc][0], Su[2 * kc][1],
                               Su[2 * kc + 1][0], Su[2 * kc + 1][1] };
            const int vrow = kc * 16 + vsub * 8 + l7;
#pragma unroll
            for (int np = 0; np < 8; np++) {
                uint32_t vf[4];
                ldsm_x4_t(vf, vB + (uint32_t)vrow * 256 +
                              (uint32_t)((((np * 2 + vnq)) ^ l7) * 16));
                mma_f16(Oacc[np * 2],     aP, vf);
                mma_f16(Oacc[np * 2 + 1], aP, vf + 2);
            }
        }

        __syncthreads();
        if (kt + 2 < nkt) { stageKV(kt & 1, kt + 2); cp_commit(); }
    }

    const float inv0 = 1.0f / l0, inv1 = 1.0f / l1;
#pragma unroll
    for (int nt = 0; nt < 16; nt++) {
        int col = h * HD + nt * 8 + lc * 2;
        *(__half2*)&outh[(size_t)grow0 * (NH * HD) + col] =
            __floats2half2_rn(Oacc[nt][0] * inv0, Oacc[nt][1] * inv0);
        *(__half2*)&outh[(size_t)(grow0 + 8) * (NH * HD) + col] =
            __floats2half2_rn(Oacc[nt][2] * inv1, Oacc[nt][3] * inv1);
    }
}

// ---------------------------------------------------------------------------
// fp16 mma.sync GEMM (NN-B): C = A[M,K] @ B[K,N], A K-major, B row-major.
// A tile 128x128B (ldsm), B tile 64 rows x 256B (ldsm.trans, flash-validated).
// BM=128, BN=128, BK=64, 8 warps 2x4. EPI: 0 fp16 plain, 1 fp32 +Aux.
// ---------------------------------------------------------------------------
constexpr int TILEA  = 128 * 128;   // bytes
constexpr int TILEBN = 64 * 256;    // bytes (== 16384)
constexpr int STGB   = TILEA + TILEBN;
constexpr int NSTAGE = 3;
constexpr int GEMM_SMEM = NSTAGE * STGB;  // 98304

template<int EPI>
__global__ __launch_bounds__(256, 2)
void mma_gemm(const __half* __restrict__ A, const __half* __restrict__ B,
              void* __restrict__ Cv, const float* __restrict__ Aux,
              int K, int lda, int ldb, int ldc) {
    const int row0 = blockIdx.y * 128;
    const int col0 = blockIdx.x * 128;

    extern __shared__ char smc[];
    const uint32_t smBase = smem_u32(smc);

    const int tid = threadIdx.x;
    const int wid = tid >> 5, lane = tid & 31;
    const int lr = lane >> 2, lc = lane & 3, l7 = lane & 7;
    const int wm = (wid & 1) * 64;
    const int wn = (wid >> 1) * 32;

    const int nkt = K / 64;
    const int aRow = wm + ((lane >> 3) & 1) * 8 + l7;
    const int aSel = (lane >> 4) & 1;
    const int vsub = (lane >> 3) & 1, vnq = (lane >> 4) & 1;
    const int cwBase = wn >> 3;

    auto stage = [&](int s, int kt) {
        const uint32_t aB = smBase + (uint32_t)(s * STGB);
        const uint32_t bB = aB + (uint32_t)TILEA;
        const __half* Ap = A + (size_t)row0 * lda + kt * 64;
        const __half* Bp = B + (size_t)(kt * 64) * ldb + col0;
#pragma unroll
        for (int j = 0; j < 4; j++) {
            int idx = j * 256 + tid, r = idx >> 3, c = idx & 7;
            uint32_t sw = (uint32_t)((c ^ (r & 7)) * 16);
            cp16(aB + (uint32_t)r * 128 + sw, Ap + (size_t)r * lda + c * 8);
        }
#pragma unroll
        for (int j = 0; j < 4; j++) {
            int idx = j * 256 + tid, r = idx >> 4, c = idx & 15;
            uint32_t sw = (uint32_t)((c ^ (r & 7)) * 16);
            cp16(bB + (uint32_t)r * 256 + sw, Bp + (size_t)r * ldb + c * 8);
        }
    };

    float acc[4][4][4];
#pragma unroll
    for (int mt = 0; mt < 4; mt++)
#pragma unroll
        for (int nt = 0; nt < 4; nt++)
#pragma unroll
            for (int i = 0; i < 4; i++) acc[mt][nt][i] = 0.f;

    stage(0, 0);
    cp_commit();
    if (nkt > 1) { stage(1, 1); cp_commit(); }

    uint32_t af[2][4][4], bf[2][4][2];
    auto loadFrags = [&](int buf, int ks, uint32_t aB4, uint32_t bB4) {
        const uint32_t ca = (uint32_t)(((ks * 2 + aSel) ^ l7) * 16);
#pragma unroll
        for (int mt = 0; mt < 4; mt++)
            ldsm_x4(af[buf][mt], aB4 + (uint32_t)(aRow + mt * 16) * 128 + ca);
        const int vrow = ks * 16 + vsub * 8 + l7;
#pragma unroll
        for (int np = 0; np < 2; np++) {
            uint32_t tmp[4];
            ldsm_x4_t(tmp, bB4 + (uint32_t)vrow * 256 +
                           (uint32_t)(((cwBase + np * 2 + vnq) ^ l7) * 16));
            bf[buf][np * 2][0] = tmp[0]; bf[buf][np * 2][1] = tmp[1];
            bf[buf][np * 2 + 1][0] = tmp[2]; bf[buf][np * 2 + 1][1] = tmp[3];
        }
    };

    int s = 0;
    for (int kt = 0; kt < nkt; kt++) {
        if (kt == nkt - 1) cp_wait<0>(); else cp_wait<1>();
        __syncthreads();
        if (kt + 2 < nkt) {
            int s2 = s + 2; if (s2 >= NSTAGE) s2 -= NSTAGE;
            stage(s2, kt + 2);
            cp_commit();
        }
        const uint32_t aB4 = smBase + (uint32_t)(s * STGB);
        const uint32_t bB4 = aB4 + (uint32_t)TILEA;
        loadFrags(0, 0, aB4, bB4);
#pragma unroll
        for (int ks = 0; ks < 4; ks++) {
            if (ks < 3) loadFrags((ks + 1) & 1, ks + 1, aB4, bB4);
            const int cb = ks & 1;
#pragma unroll
            for (int mt = 0; mt < 4; mt++)
#pragma unroll
                for (int nt = 0; nt < 4; nt++)
                    mma_f16(acc[mt][nt], af[cb][mt], bf[cb][nt]);
        }
        if (++s >= NSTAGE) s -= NSTAGE;
    }

    __half* Ch = (__half*)Cv;
    float*  Cf = (float*)Cv;
#pragma unroll
    for (int mt = 0; mt < 4; mt++) {
        const int ra = row0 + wm + mt * 16 + lr;
        const int rb = ra + 8;
#pragma unroll
        for (int nt = 0; nt < 4; nt++) {
            const int c = col0 + wn + nt * 8 + lc * 2;
            float* a4 = acc[mt][nt];
            const size_t ia = (size_t)ra * ldc + c;
            const size_t ib = (size_t)rb * ldc + c;
            if (EPI == 0) {
                *(__half2*)&Ch[ia] = __floats2half2_rn(a4[0], a4[1]);
                *(__half2*)&Ch[ib] = __floats2half2_rn(a4[2], a4[3]);
            } else {
                float2 xa = *(const float2*)&Aux[ia], xb = *(const float2*)&Aux[ib];
                *(float2*)&Cf[ia] = make_float2(a4[0] + xa.x, a4[1] + xa.y);
                *(float2*)&Cf[ib] = make_float2(a4[2] + xb.x, a4[3] + xb.y);
            }
        }
    }
}

// ---------------------------------------------------------------------------
// Fused gate+up MLP with NN-B (trans-ldsm) weights. 128 rows x 64 ff-cols.
// Stage: A 16KB + Bg 8KB + Bu 8KB = 32KB (B tiles 64 rows x 128B).
// ---------------------------------------------------------------------------
__global__ __launch_bounds__(256, 2)
void mma_mlp(const __half* __restrict__ A, const __half* __restrict__ Bg,
             const __half* __restrict__ Bu, __half* __restrict__ C) {
    const int row0 = blockIdx.y * 128;
    const int ffc0 = blockIdx.x * 64;

    extern __shared__ char smc[];
    const uint32_t smBase = smem_u32(smc);

    const int tid = threadIdx.x;
    const int wid = tid >> 5, lane = tid & 31;
    const int lr = lane >> 2, lc = lane & 3, l7 = lane & 7;
    const int role = wid >> 2;
    const int w2 = wid & 3;
    const int wm = (w2 & 1) * 64;
    const int wn = (w2 >> 1) * 32;

    const int aRow = wm + ((lane >> 3) & 1) * 8 + l7;
    const int aSel = (lane >> 4) & 1;
    const int vsub = (lane >> 3) & 1, vnq = (lane >> 4) & 1;
    const int cwBase = wn >> 3;

    constexpr int nkt = DIM / 64;

    auto stage = [&](int s, int kt) {
        const uint32_t aB = smBase + (uint32_t)(s * STGB);
        const uint32_t gB = aB + (uint32_t)TILEA;
        const uint32_t uB = gB + 8192u;
        const __half* Ap = A + (size_t)row0 * DIM + kt * 64;
        const __half* Gp = Bg + (size_t)(kt * 64) * FF + ffc0;
        const __half* Up = Bu + (size_t)(kt * 64) * FF + ffc0;
#pragma unroll
        for (int j = 0; j < 4; j++) {
            int idx = j * 256 + tid, r = idx >> 3, c = idx & 7;
            uint32_t sw = (uint32_t)((c ^ (r & 7)) * 16);
            cp16(aB + (uint32_t)r * 128 + sw, Ap + (size_t)r * DIM + c * 8);
        }
#pragma unroll
        for (int j = 0; j < 2; j++) {
            int idx = j * 256 + tid, r = idx >> 3, c = idx & 7;  // r 0..63
            uint32_t sw = (uint32_t)((c ^ (r & 7)) * 16);
            cp16(gB + (uint32_t)r * 128 + sw, Gp + (size_t)r * FF + c * 8);
            cp16(uB + (uint32_t)r * 128 + sw, Up + (size_t)r * FF + c * 8);
        }
    };

    float acc[4][4][4];
#pragma unroll
    for (int mt = 0; mt < 4; mt++)
#pragma unroll
        for (int nt = 0; nt < 4; nt++)
#pragma unroll
            for (int i = 0; i < 4; i++) acc[mt][nt][i] = 0.f;

    stage(0, 0);
    cp_commit();
    stage(1, 1);
    cp_commit();

    uint32_t af[2][4][4], bf[2][4][2];
    const uint32_t bOff = (uint32_t)TILEA + (role ? 8192u : 0u);

    auto loadFrags = [&](int buf, int ks, uint32_t aB4, uint32_t bB4) {
        const uint32_t ca = (uint32_t)(((ks * 2 + aSel) ^ l7) * 16);
#pragma unroll
        for (int mt = 0; mt < 4; mt++)
            ldsm_x4(af[buf][mt], aB4 + (uint32_t)(aRow + mt * 16) * 128 + ca);
        const int vrow = ks * 16 + vsub * 8 + l7;
#pragma unroll
        for (int np = 0; np < 2; np++) {
            uint32_t tmp[4];
            ldsm_x4_t(tmp, bB4 + (uint32_t)vrow * 128 +
                           (uint32_t)(((cwBase + np * 2 + vnq) ^ l7) * 16));
            bf[buf][np * 2][0] = tmp[0]; bf[buf][np * 2][1] = tmp[1];
            bf[buf][np * 2 + 1][0] = tmp[2]; bf[buf][np * 2 + 1][1] = tmp[3];
        }
    };

    int s = 0;
    for (int kt = 0; kt < nkt; kt++) {
        if (kt == nkt - 1) cp_wait<0>(); else cp_wait<1>();
        __syncthreads();
        if (kt + 2 < nkt) {
            int s2 = s + 2; if (s2 >= NSTAGE) s2 -= NSTAGE;
            stage(s2, kt + 2);
            cp_commit();
        }
        const uint32_t aB4 = smBase + (uint32_t)(s * STGB);
        const uint32_t bB4 = aB4 + bOff;
        loadFrags(0, 0, aB4, bB4);
#pragma unroll
        for (int ks = 0; ks < 4; ks++) {
            if (ks < 3) loadFrags((ks + 1) & 1, ks + 1, aB4, bB4);
            const int cb = ks & 1;
#pragma unroll
            for (int mt = 0; mt < 4; mt++)
#pragma unroll
                for (int nt = 0; nt < 4; nt++)
                    mma_f16(acc[mt][nt], af[cb][mt], bf[cb][nt]);
        }
        if (++s >= NSTAGE) s -= NSTAGE;
    }

    __syncthreads();
    float* gsm = (float*)smc;
    if (role == 0) {
#pragma unroll
        for (int mt = 0; mt < 4; mt++) {
            const int ra = wm + mt * 16 + lr, rb = ra + 8;
#pragma unroll
            for (int nt = 0; nt < 4; nt++) {
                const int cl = wn + nt * 8 + lc * 2;
                float* a4 = acc[mt][nt];
                gsm[ra * 66 + cl] = a4[0]; gsm[ra * 66 + cl + 1] = a4[1];
                gsm[rb * 66 + cl] = a4[2]; gsm[rb * 66 + cl + 1] = a4[3];
            }
        }
    }
    __syncthreads();
    if (role == 1) {
#pragma unroll
        for (int mt = 0; mt < 4; mt++) {
            const int ra = wm + mt * 16 + lr, rb = ra + 8;
#pragma unroll
            for (int nt = 0; nt < 4; nt++) {
                const int cl = wn + nt * 8 + lc * 2;
                float* a4 = acc[mt][nt];
                float g0 = gsm[ra * 66 + cl], g1 = gsm[ra * 66 + cl + 1];
                float g2 = gsm[rb * 66 + cl], g3 = gsm[rb * 66 + cl + 1];
                size_t ia = (size_t)(row0 + ra) * FF + ffc0 + cl;
                size_t ib = (size_t)(row0 + rb) * FF + ffc0 + cl;
                *(__half2*)&C[ia] = __floats2half2_rn(silu(g0) * a4[0], silu(g1) * a4[1]);
                *(__half2*)&C[ib] = __floats2half2_rn(silu(g2) * a4[2], silu(g3) * a4[3]);
            }
        }
    }
}

// ---------------------------------------------------------------------------
extern "C" void kernel_launch(void* const* d_in, const int* in_sizes, int n_in,
                              void* d_out, int out_size) {
    (void)in_sizes; (void)n_in; (void)out_size;
    const float* x   = (const float*)d_in[0];
    const float* ln1 = (const float*)d_in[2];
    const float* Wq  = (const float*)d_in[3];
    const float* Wk  = (const float*)d_in[4];
    const float* Wv  = (const float*)d_in[5];
    const float* Wo  = (const float*)d_in[6];
    const float* ln2 = (const float*)d_in[7];
    const float* Wg  = (const float*)d_in[8];
    const float* Wu  = (const float*)d_in[9];
    const float* Wd  = (const float*)d_in[10];
    float* out = (float*)d_out;

    __half *h1h, *qkvh, *ath, *h2h, *mmh;
    __half *Wqkv16, *Wo16, *Wg16, *Wu16, *Wd16;
    float *x2;
    cudaGetSymbolAddress((void**)&h1h, g_h1h);   cudaGetSymbolAddress((void**)&qkvh, g_qkvh);
    cudaGetSymbolAddress((void**)&ath, g_ath);   cudaGetSymbolAddress((void**)&x2, g_x2);
    cudaGetSymbolAddress((void**)&h2h, g_h2h);   cudaGetSymbolAddress((void**)&mmh, g_mmh);
    cudaGetSymbolAddress((void**)&Wqkv16, g_Wqkv16); cudaGetSymbolAddress((void**)&Wo16, g_Wo16);
    cudaGetSymbolAddress((void**)&Wg16, g_Wg16);     cudaGetSymbolAddress((void**)&Wu16, g_Wu16);
    cudaGetSymbolAddress((void**)&Wd16, g_Wd16);

    cudaFuncSetAttribute(mma_gemm<0>, cudaFuncAttributeMaxDynamicSharedMemorySize, GEMM_SMEM);
    cudaFuncSetAttribute(mma_gemm<1>, cudaFuncAttributeMaxDynamicSharedMemorySize, GEMM_SMEM);
    cudaFuncSetAttribute(mma_mlp, cudaFuncAttributeMaxDynamicSharedMemorySize, GEMM_SMEM);
    cudaFuncSetAttribute(flash_attn, cudaFuncAttributeMaxDynamicSharedMemorySize, FL_SMEM);

    const float iscale = 0.08838834764831843f;  // 1/sqrt(128)

    // streaming fp32->fp16 converts (no transposition). QKV packs columns.
    convert_wh<<<4096, 256>>>(Wq, Wqkv16,          DIM, DIM, QKVN);
    convert_wh<<<1024, 256>>>(Wk, Wqkv16 + 2048,   DIM, 512, QKVN);
    convert_wh<<<1024, 256>>>(Wv, Wqkv16 + 2560,   DIM, 512, QKVN);
    convert_wh<<<4096, 256>>>(Wo, Wo16,            DIM, DIM, DIM);
    convert_wh<<<8192, 256>>>(Wg, Wg16,            DIM, FF,  FF);
    convert_wh<<<8192, 256>>>(Wu, Wu16,            DIM, FF,  FF);
    convert_wh<<<8192, 256>>>(Wd, Wd16,            FF,  DIM, DIM);
    init_invf_kernel<<<1, 64>>>();
    rope_table_kernel<<<SEQ, 64>>>();

    rmsnorm_h<<<SEQ, 256>>>(x, ln1, h1h);

    // fused QKV projection: qkv[S][3072]
    mma_gemm<0><<<dim3(QKVN / 128, 16, 1), 256, GEMM_SMEM>>>(
        h1h, Wqkv16, qkvh, nullptr, DIM, DIM, QKVN, QKVN);

    rope_apply_h<<<dim3(SEQ, NH + NKV), 64>>>(qkvh);

    // fused flash attention -> ath [S][NH*HD]
    flash_attn<<<dim3(16, NH), 256, FL_SMEM>>>(qkvh, ath, iscale);

    // x2 = at @ Wo + x (fp32)
    mma_gemm<1><<<dim3(16, 16, 1), 256, GEMM_SMEM>>>(
        ath, Wo16, x2, x, DIM, DIM, DIM, DIM);

    rmsnorm_h<<<SEQ, 256>>>(x2, ln2, h2h);

    // fused gate+up MLP
    mma_mlp<<<dim3(FF / 64, 16, 1), 256, GEMM_SMEM>>>(h2h, Wg16, Wu16, mmh);

    // out = mm @ Wd + x2 (fp32)
    mma_gemm<1><<<dim3(16, 16, 1), 256, GEMM_SMEM>>>(
        mmh, Wd16, out, x2, FF, FF, DIM, DIM);
}